// round 14
// baseline (speedup 1.0000x reference)
#include <cuda_runtime.h>
#include <cuda_fp16.h>
#include <cstdint>

#define NTH    256
#define NCTA   128
#define TSTEPS 128

// ---- SMEM byte offsets ----
#define OFF_FRAG 0          // 612 frags x 256 B
#define OFF_X    156672     // 128 x 128 B fp16 (SW128)
#define OFF_H0   173056
#define OFF_H1   189440
#define OFF_H2   205824
#define OFF_BR   222208     // 3 x 64 f32
#define OFF_BZ   222976
#define OFF_BIN  223744
#define OFF_BHN  224512
#define OFF_BE   225280     // 64 f32
#define OFF_BO   225536     // 2 f32
#define SMEM_SZ  225600

#define SWZ(o) ((uint32_t)(o) ^ ((((uint32_t)(o)) >> 3) & 0x70u))

static __device__ __forceinline__ uint32_t smem_u32(const void* p) {
    uint32_t a;
    asm("{ .reg .u64 t; cvta.to.shared.u64 t, %1; cvt.u32.u64 %0, t; }" : "=r"(a) : "l"(p));
    return a;
}
static __device__ __forceinline__ void ldmA(uint32_t* a, uint32_t addr) {
    asm volatile("ldmatrix.sync.aligned.m8n8.x4.shared.b16 {%0,%1,%2,%3}, [%4];"
                 : "=r"(a[0]), "=r"(a[1]), "=r"(a[2]), "=r"(a[3]) : "r"(addr));
}
static __device__ __forceinline__ uint2 ldB(uint32_t a) {
    uint2 r;
    asm volatile("ld.shared.v2.b32 {%0,%1}, [%2];" : "=r"(r.x), "=r"(r.y) : "r"(a));
    return r;
}
static __device__ __forceinline__ void mma16816(float* c, const uint32_t* a, uint2 b) {
    asm volatile(
        "mma.sync.aligned.m16n8k16.row.col.f32.f16.f16.f32 "
        "{%0,%1,%2,%3}, {%4,%5,%6,%7}, {%8,%9}, {%0,%1,%2,%3};"
        : "+f"(c[0]), "+f"(c[1]), "+f"(c[2]), "+f"(c[3])
        : "r"(a[0]), "r"(a[1]), "r"(a[2]), "r"(a[3]), "r"(b.x), "r"(b.y));
}
// loads 4 k-tiles (16 regs) of a 16x64 fp16 A tile (SW128-swizzled rows)
static __device__ __forceinline__ void ldA64(uint32_t* A, uint32_t rowbase,
                                             uint32_t ub, uint32_t xr) {
#pragma unroll
    for (int kt = 0; kt < 4; kt++)
        ldmA(A + kt * 4, rowbase + (((((uint32_t)kt << 1) | ub)) ^ xr) * 16u);
}
static __device__ __forceinline__ uint32_t packh2(float a, float b) {
    __half2 h = __floats2half2_rn(a, b);
    return *(uint32_t*)&h;
}
static __device__ __forceinline__ float ex2f(float x) {
    float y; asm("ex2.approx.f32 %0, %1;" : "=f"(y) : "f"(x)); return y;
}
static __device__ __forceinline__ float rcpf(float x) {
    float y; asm("rcp.approx.f32 %0, %1;" : "=f"(y) : "f"(x)); return y;
}
static __device__ __forceinline__ float sigm(float x) {
    return rcpf(1.0f + ex2f(-1.4426950408889634f * x));
}
static __device__ __forceinline__ float tanhp(float x) {
    return __fmaf_rn(2.0f, rcpf(1.0f + ex2f(-2.8853900817779268f * x)), -1.0f);
}
static __device__ __forceinline__ float gru1(float rp, float zp, float ni, float nh, float ho) {
    float r = sigm(rp);
    float z = sigm(zp);
    float n = tanhp(__fmaf_rn(r, nh, ni));
    return __fmaf_rn(z, ho - n, n);
}

__global__ void __launch_bounds__(NTH, 1)
futuretraj_kernel(const float* __restrict__ enc,
                  const float* __restrict__ emb_w, const float* __restrict__ emb_b,
                  const float* __restrict__ w_ih,  const float* __restrict__ w_hh,
                  const float* __restrict__ b_ih,  const float* __restrict__ b_hh,
                  const float* __restrict__ out_w, const float* __restrict__ out_b,
                  float* __restrict__ out) {
    extern __shared__ char smem[];
    const uint32_t sb = smem_u32(smem);
    const int tid = threadIdx.x;
    const int ln  = tid & 31;
    const int j   = tid >> 5;                 // warp id: owns hidden cols 8j..8j+7
    const int g   = ln >> 2;
    const int tq  = ln & 3;
    const uint32_t rl = (uint32_t)((ln & 7) + ((ln >> 3) & 1) * 8);
    const uint32_t ub = (uint32_t)((ln >> 4) & 1);
    const uint32_t xr = (uint32_t)(ln & 7);
    const int row0 = blockIdx.x * 128;

    // ============ one-time staging: weight fragments (fp32 -> fp16) ============
    // frag order: [0,32) emb (nt*4+kt) ; [32,608) layers: lay*192 + (isWh?96:0) + nt*4+kt ;
    // [608,612) out (kt). Each frag = 32 lanes x {b32 lo, b32 hi}.
    for (int i = tid; i < 612 * 32; i += NTH) {
        int f = i >> 5, la = i & 31;
        int gq = la >> 2, tt = la & 3;
        float v0 = 0.f, v1 = 0.f, v2 = 0.f, v3 = 0.f;
        if (f < 32) {
            int nt = f >> 2, kt = f & 3;
            const float* p = emb_w + (nt * 8 + gq) * 64 + kt * 16 + 2 * tt;
            v0 = p[0]; v1 = p[1]; v2 = p[8]; v3 = p[9];
        } else if (f < 608) {
            int r = f - 32;
            int lay = r / 192; r -= lay * 192;
            const float* W = (r >= 96) ? w_hh : w_ih;
            if (r >= 96) r -= 96;
            int nt = r >> 2, kt = r & 3;
            const float* p = W + (size_t)lay * 192 * 64 + (nt * 8 + gq) * 64 + kt * 16 + 2 * tt;
            v0 = p[0]; v1 = p[1]; v2 = p[8]; v3 = p[9];
        } else {
            int kt = f - 608;
            if (gq < 2) {
                const float* p = out_w + gq * 64 + kt * 16 + 2 * tt;
                v0 = p[0]; v1 = p[1]; v2 = p[8]; v3 = p[9];
            }
        }
        uint32_t* d = (uint32_t*)(smem + OFF_FRAG + f * 256 + la * 8);
        d[0] = packh2(v0, v1);
        d[1] = packh2(v2, v3);
    }
    // biases
    for (int i = tid; i < 3 * 64; i += NTH) {
        int lay = i >> 6, c = i & 63;
        ((float*)(smem + OFF_BR))[i]  = b_ih[lay * 192 + c]       + b_hh[lay * 192 + c];
        ((float*)(smem + OFF_BZ))[i]  = b_ih[lay * 192 + 64 + c]  + b_hh[lay * 192 + 64 + c];
        ((float*)(smem + OFF_BIN))[i] = b_ih[lay * 192 + 128 + c];
        ((float*)(smem + OFF_BHN))[i] = b_hh[lay * 192 + 128 + c];
    }
    for (int i = tid; i < 64; i += NTH) ((float*)(smem + OFF_BE))[i] = emb_b[i];
    if (tid < 2) ((float*)(smem + OFF_BO))[tid] = out_b[tid];
    // h0 (all layers) = encoding, fp16 SW128
    for (int i = tid; i < 128 * 64; i += NTH) {
        int r = i >> 6, c = i & 63;
        __half v = __float2half_rn(enc[(size_t)row0 * 64 + i]);
        uint32_t o = SWZ(r * 128 + c * 2);
        *(__half*)(smem + OFF_H0 + o) = v;
        *(__half*)(smem + OFF_H1 + o) = v;
        *(__half*)(smem + OFF_H2 + o) = v;
    }
    __syncthreads();

    // ---- persistent per-warp fragments / biases ----
    const uint32_t fb = sb + OFF_FRAG;
    const uint32_t l8 = (uint32_t)ln * 8u;
    uint2 EMBF[4], OUTF[4];
#pragma unroll
    for (int kt = 0; kt < 4; kt++) {
        EMBF[kt] = ldB(fb + (uint32_t)(j * 4 + kt) * 256u + l8);
        OUTF[kt] = ldB(fb + (uint32_t)(608 + kt) * 256u + l8);
    }
    const float be0 = ((const float*)(smem + OFF_BE))[8 * j + 2 * tq];
    const float be1 = ((const float*)(smem + OFF_BE))[8 * j + 2 * tq + 1];
    const float bo0 = ((const float*)(smem + OFF_BO))[0];
    const float bo1 = ((const float*)(smem + OFF_BO))[1];

    const uint32_t hOffs[3] = {OFF_H0, OFF_H1, OFF_H2};
    const uint32_t lanerow = rl * 128u;     // byte offset of lane row within an m-tile
    const uint32_t stAddr0 = (uint32_t)g * 128u + (uint32_t)((j ^ g) << 4) + (uint32_t)(4 * tq);

#pragma unroll 1
    for (int step = 0; step < TSTEPS; step++) {
        // ===== phase E: emb(step) from H2; out(step-1) fused at mt==j =====
#pragma unroll 1
        for (int mt = 0; mt < 8; mt++) {
            uint32_t Ah[16];
            ldA64(Ah, sb + OFF_H2 + (uint32_t)mt * 2048u + lanerow, ub, xr);
            if (mt == j && step > 0) {
                float co[4] = {bo0, bo1, bo0, bo1};
#pragma unroll
                for (int kt = 0; kt < 4; kt++) mma16816(co, Ah + 4 * kt, OUTF[kt]);
                if (tq == 0) {
                    float* o0 = out + ((size_t)(row0 + j * 16 + g)) * (TSTEPS * 2) + (step - 1) * 2;
                    *(float2*)o0 = make_float2(co[0], co[1]);
                    *(float2*)(o0 + 8 * (TSTEPS * 2)) = make_float2(co[2], co[3]);
                }
            }
            float ce[4] = {be0, be1, be0, be1};
#pragma unroll
            for (int kt = 0; kt < 4; kt++) mma16816(ce, Ah + 4 * kt, EMBF[kt]);
            uint32_t a = OFF_X + (uint32_t)mt * 2048u + stAddr0;
            *(uint32_t*)(smem + a)         = packh2(ce[0], ce[1]);
            *(uint32_t*)(smem + a + 1024u) = packh2(ce[2], ce[3]);
        }
        __syncthreads();

        // ===== GRU layers =====
#pragma unroll 1
        for (int lay = 0; lay < 3; lay++) {
            const uint32_t wb = fb + (uint32_t)(32 + lay * 192) * 256u + l8;
            uint2 WIR[4], WIZ[4], WIN[4], WHR[4], WHZ[4], WHN[4];
#pragma unroll
            for (int kt = 0; kt < 4; kt++) {
                WIR[kt] = ldB(wb + (uint32_t)(j * 4 + kt) * 256u);
                WIZ[kt] = ldB(wb + (uint32_t)((j + 8) * 4 + kt) * 256u);
                WIN[kt] = ldB(wb + (uint32_t)((j + 16) * 4 + kt) * 256u);
                WHR[kt] = ldB(wb + (uint32_t)(96 + j * 4 + kt) * 256u);
                WHZ[kt] = ldB(wb + (uint32_t)(96 + (j + 8) * 4 + kt) * 256u);
                WHN[kt] = ldB(wb + (uint32_t)(96 + (j + 16) * 4 + kt) * 256u);
            }
            const float br0 = ((const float*)(smem + OFF_BR))[lay * 64 + 8 * j + 2 * tq];
            const float br1 = ((const float*)(smem + OFF_BR))[lay * 64 + 8 * j + 2 * tq + 1];
            const float bz0 = ((const float*)(smem + OFF_BZ))[lay * 64 + 8 * j + 2 * tq];
            const float bz1 = ((const float*)(smem + OFF_BZ))[lay * 64 + 8 * j + 2 * tq + 1];
            const float bi0 = ((const float*)(smem + OFF_BIN))[lay * 64 + 8 * j + 2 * tq];
            const float bi1 = ((const float*)(smem + OFF_BIN))[lay * 64 + 8 * j + 2 * tq + 1];
            const float bh0 = ((const float*)(smem + OFF_BHN))[lay * 64 + 8 * j + 2 * tq];
            const float bh1 = ((const float*)(smem + OFF_BHN))[lay * 64 + 8 * j + 2 * tq + 1];
            const uint32_t xsrc = sb + ((lay == 0) ? OFF_X : hOffs[lay - 1]);
            const uint32_t hsrc = sb + hOffs[lay];

            uint32_t stash[16];
#pragma unroll 1
            for (int mt = 0; mt < 8; mt++) {
                uint32_t Ax[16], Ah[16];
                ldA64(Ax, xsrc + (uint32_t)mt * 2048u + lanerow, ub, xr);
                ldA64(Ah, hsrc + (uint32_t)mt * 2048u + lanerow, ub, xr);
                float cr[4] = {br0, br1, br0, br1};
                float cz[4] = {bz0, bz1, bz0, bz1};
                float ci[4] = {bi0, bi1, bi0, bi1};
                float ch[4] = {bh0, bh1, bh0, bh1};
#pragma unroll
                for (int kt = 0; kt < 4; kt++) {
                    mma16816(cr, Ax + 4 * kt, WIR[kt]);
                    mma16816(cr, Ah + 4 * kt, WHR[kt]);
                    mma16816(cz, Ax + 4 * kt, WIZ[kt]);
                    mma16816(cz, Ah + 4 * kt, WHZ[kt]);
                    mma16816(ci, Ax + 4 * kt, WIN[kt]);
                    mma16816(ch, Ah + 4 * kt, WHN[kt]);
                }
                // h_old for this warp's 2 columns, straight from the A_h fragment
                uint32_t hoL = Ah[(j >> 1) * 4 + ((j & 1) << 1)];
                uint32_t hoH = Ah[(j >> 1) * 4 + ((j & 1) << 1) + 1];
                float2 f0 = __half22float2(*(__half2*)&hoL);
                float2 f1 = __half22float2(*(__half2*)&hoH);
                float h0 = gru1(cr[0], cz[0], ci[0], ch[0], f0.x);
                float h1 = gru1(cr[1], cz[1], ci[1], ch[1], f0.y);
                float h2 = gru1(cr[2], cz[2], ci[2], ch[2], f1.x);
                float h3 = gru1(cr[3], cz[3], ci[3], ch[3], f1.y);
                stash[2 * mt]     = packh2(h0, h1);
                stash[2 * mt + 1] = packh2(h2, h3);
            }
            __syncthreads();   // all reads of h_l done
#pragma unroll
            for (int mt = 0; mt < 8; mt++) {
                uint32_t a = hOffs[lay] + (uint32_t)mt * 2048u + stAddr0;
                *(uint32_t*)(smem + a)         = stash[2 * mt];
                *(uint32_t*)(smem + a + 1024u) = stash[2 * mt + 1];
            }
            __syncthreads();   // h_l updated, visible to all
        }
    }

    // ===== final out (t = 127) from H2 =====
    {
        uint32_t Ah[16];
        ldA64(Ah, sb + OFF_H2 + (uint32_t)j * 2048u + lanerow, ub, xr);
        float co[4] = {bo0, bo1, bo0, bo1};
#pragma unroll
        for (int kt = 0; kt < 4; kt++) mma16816(co, Ah + 4 * kt, OUTF[kt]);
        if (tq == 0) {
            float* o0 = out + ((size_t)(row0 + j * 16 + g)) * (TSTEPS * 2) + 127 * 2;
            *(float2*)o0 = make_float2(co[0], co[1]);
            *(float2*)(o0 + 8 * (TSTEPS * 2)) = make_float2(co[2], co[3]);
        }
    }
}

extern "C" void kernel_launch(void* const* d_in, const int* in_sizes, int n_in,
                              void* d_out, int out_size) {
    (void)in_sizes; (void)n_in; (void)out_size;
    const float* enc   = (const float*)d_in[0];
    const float* emb_w = (const float*)d_in[1];
    const float* emb_b = (const float*)d_in[2];
    const float* w_ih  = (const float*)d_in[3];
    const float* w_hh  = (const float*)d_in[4];
    const float* b_ih  = (const float*)d_in[5];
    const float* b_hh  = (const float*)d_in[6];
    const float* out_w = (const float*)d_in[7];
    const float* out_b = (const float*)d_in[8];
    float* out = (float*)d_out;

    cudaFuncSetAttribute(futuretraj_kernel,
                         cudaFuncAttributeMaxDynamicSharedMemorySize, SMEM_SZ);
    futuretraj_kernel<<<NCTA, NTH, SMEM_SZ>>>(
        enc, emb_w, emb_b, w_ih, w_hh, b_ih, b_hh, out_w, out_b, out);
}

// round 15
// speedup vs baseline: 1.2672x; 1.2672x over previous
#include <cuda_runtime.h>
#include <cuda_fp16.h>
#include <cstdint>

#define NTH    512
#define NCTA   128
#define TSTEPS 128

// ---- SMEM byte offsets ----
#define OFF_FRAG 0          // 612 frags x 256 B
#define OFF_X    156672     // 128 x 128 B fp16 (SW128)
#define OFF_H0   173056
#define OFF_H1   189440
#define OFF_H2   205824
#define OFF_BR   222208     // 3 x 64 f32
#define OFF_BZ   222976
#define OFF_BIN  223744
#define OFF_BHN  224512
#define OFF_BE   225280     // 64 f32
#define OFF_BO   225536     // 2 f32
#define SMEM_SZ  225600

#define SWZ(o) ((uint32_t)(o) ^ ((((uint32_t)(o)) >> 3) & 0x70u))

static __device__ __forceinline__ uint32_t smem_u32(const void* p) {
    uint32_t a;
    asm("{ .reg .u64 t; cvta.to.shared.u64 t, %1; cvt.u32.u64 %0, t; }" : "=r"(a) : "l"(p));
    return a;
}
static __device__ __forceinline__ void ldmA(uint32_t* a, uint32_t addr) {
    asm volatile("ldmatrix.sync.aligned.m8n8.x4.shared.b16 {%0,%1,%2,%3}, [%4];"
                 : "=r"(a[0]), "=r"(a[1]), "=r"(a[2]), "=r"(a[3]) : "r"(addr));
}
static __device__ __forceinline__ uint2 ldB(uint32_t a) {
    uint2 r;
    asm volatile("ld.shared.v2.b32 {%0,%1}, [%2];" : "=r"(r.x), "=r"(r.y) : "r"(a));
    return r;
}
static __device__ __forceinline__ void mma16816(float* c, const uint32_t* a, uint2 b) {
    asm volatile(
        "mma.sync.aligned.m16n8k16.row.col.f32.f16.f16.f32 "
        "{%0,%1,%2,%3}, {%4,%5,%6,%7}, {%8,%9}, {%0,%1,%2,%3};"
        : "+f"(c[0]), "+f"(c[1]), "+f"(c[2]), "+f"(c[3])
        : "r"(a[0]), "r"(a[1]), "r"(a[2]), "r"(a[3]), "r"(b.x), "r"(b.y));
}
static __device__ __forceinline__ uint32_t packh2(float a, float b) {
    __half2 h = __floats2half2_rn(a, b);
    return *(uint32_t*)&h;
}
static __device__ __forceinline__ float tanha(float x) {
    float y; asm("tanh.approx.f32 %0, %1;" : "=f"(y) : "f"(x)); return y;
}
static __device__ __forceinline__ float sigm(float x) {
    return __fmaf_rn(0.5f, tanha(0.5f * x), 0.5f);
}
static __device__ __forceinline__ float gru1(float rp, float zp, float ni, float nh, float ho) {
    float r = sigm(rp);
    float z = sigm(zp);
    float n = tanha(__fmaf_rn(r, nh, ni));
    return __fmaf_rn(z, ho - n, n);
}
static __device__ __forceinline__ void barG(uint32_t id) {
    asm volatile("bar.sync %0, %1;" :: "r"(id), "r"(256u) : "memory");
}

__global__ void __launch_bounds__(NTH, 1)
futuretraj_kernel(const float* __restrict__ enc,
                  const float* __restrict__ emb_w, const float* __restrict__ emb_b,
                  const float* __restrict__ w_ih,  const float* __restrict__ w_hh,
                  const float* __restrict__ b_ih,  const float* __restrict__ b_hh,
                  const float* __restrict__ out_w, const float* __restrict__ out_b,
                  float* __restrict__ out) {
    extern __shared__ char smem[];
    const uint32_t sb = smem_u32(smem);
    const int tid = threadIdx.x;
    const int ln  = tid & 31;
    const int w   = tid >> 5;                 // 16 warps
    const int mg  = w >> 3;                   // m-group: rows [mg*64, mg*64+64)
    const int nj  = w & 7;                    // n-group: hidden cols 8nj..8nj+7
    const int g   = ln >> 2;
    const int tq  = ln & 3;
    const uint32_t rl = (uint32_t)((ln & 7) + ((ln >> 3) & 1) * 8);
    const uint32_t ub = (uint32_t)((ln >> 4) & 1);
    const uint32_t xr = (uint32_t)(ln & 7);
    const int row0 = blockIdx.x * 128;
    const uint32_t bid = (uint32_t)(1 + mg);

    // ============ one-time staging: weight fragments (fp32 -> fp16) ============
    for (int i = tid; i < 612 * 32; i += NTH) {
        int f = i >> 5, la = i & 31;
        int gq = la >> 2, tt = la & 3;
        float v0 = 0.f, v1 = 0.f, v2 = 0.f, v3 = 0.f;
        if (f < 32) {
            int nt = f >> 2, kt = f & 3;
            const float* p = emb_w + (nt * 8 + gq) * 64 + kt * 16 + 2 * tt;
            v0 = p[0]; v1 = p[1]; v2 = p[8]; v3 = p[9];
        } else if (f < 608) {
            int r = f - 32;
            int lay = r / 192; r -= lay * 192;
            const float* W = (r >= 96) ? w_hh : w_ih;
            if (r >= 96) r -= 96;
            int nt = r >> 2, kt = r & 3;
            const float* p = W + (size_t)lay * 192 * 64 + (nt * 8 + gq) * 64 + kt * 16 + 2 * tt;
            v0 = p[0]; v1 = p[1]; v2 = p[8]; v3 = p[9];
        } else {
            int kt = f - 608;
            if (gq < 2) {
                const float* p = out_w + gq * 64 + kt * 16 + 2 * tt;
                v0 = p[0]; v1 = p[1]; v2 = p[8]; v3 = p[9];
            }
        }
        uint32_t* d = (uint32_t*)(smem + OFF_FRAG + f * 256 + la * 8);
        d[0] = packh2(v0, v1);
        d[1] = packh2(v2, v3);
    }
    for (int i = tid; i < 3 * 64; i += NTH) {
        int lay = i >> 6, c = i & 63;
        ((float*)(smem + OFF_BR))[i]  = b_ih[lay * 192 + c]       + b_hh[lay * 192 + c];
        ((float*)(smem + OFF_BZ))[i]  = b_ih[lay * 192 + 64 + c]  + b_hh[lay * 192 + 64 + c];
        ((float*)(smem + OFF_BIN))[i] = b_ih[lay * 192 + 128 + c];
        ((float*)(smem + OFF_BHN))[i] = b_hh[lay * 192 + 128 + c];
    }
    for (int i = tid; i < 64; i += NTH) ((float*)(smem + OFF_BE))[i] = emb_b[i];
    if (tid < 2) ((float*)(smem + OFF_BO))[tid] = out_b[tid];
    for (int i = tid; i < 128 * 64; i += NTH) {
        int r = i >> 6, c = i & 63;
        __half v = __float2half_rn(enc[(size_t)row0 * 64 + i]);
        uint32_t o = SWZ(r * 128 + c * 2);
        *(__half*)(smem + OFF_H0 + o) = v;
        *(__half*)(smem + OFF_H1 + o) = v;
        *(__half*)(smem + OFF_H2 + o) = v;
    }
    __syncthreads();

    const uint32_t fb = sb + OFF_FRAG;
    const uint32_t l8 = (uint32_t)ln * 8u;
    const float be0 = ((const float*)(smem + OFF_BE))[8 * nj + 2 * tq];
    const float be1 = ((const float*)(smem + OFF_BE))[8 * nj + 2 * tq + 1];
    const float bo0 = ((const float*)(smem + OFF_BO))[0];
    const float bo1 = ((const float*)(smem + OFF_BO))[1];

    const uint32_t hOffs[3] = {OFF_H0, OFF_H1, OFF_H2};
    const uint32_t lanerow = rl * 128u;
    const uint32_t stAddr0 = (uint32_t)g * 128u + (uint32_t)((nj ^ g) << 4) + (uint32_t)(4 * tq);
    const int mt0 = mg * 4;
    const int outMt = (nj < 4) ? (mt0 + nj) : -1;   // which m-tile this warp projects

#pragma unroll 1
    for (int step = 0; step < TSTEPS; step++) {
        // ===== phase E: emb(step) from H2; out(step-1) fused =====
        {
            uint2 EMBF[4], OUTF[4];
#pragma unroll
            for (int kt = 0; kt < 4; kt++) {
                EMBF[kt] = ldB(fb + (uint32_t)(nj * 4 + kt) * 256u + l8);
                OUTF[kt] = ldB(fb + (uint32_t)(608 + kt) * 256u + l8);
            }
#pragma unroll 1
            for (int m = 0; m < 4; m++) {
                const int mt = mt0 + m;
                const uint32_t abase = sb + OFF_H2 + (uint32_t)mt * 2048u + lanerow;
                float ce[4] = {be0, be1, be0, be1};
                if (mt == outMt) {
                    float co[4] = {bo0, bo1, bo0, bo1};
#pragma unroll
                    for (int kt = 0; kt < 4; kt++) {
                        uint32_t ah[4];
                        ldmA(ah, abase + (((((uint32_t)kt << 1) | ub)) ^ xr) * 16u);
                        mma16816(ce, ah, EMBF[kt]);
                        mma16816(co, ah, OUTF[kt]);
                    }
                    if (step > 0 && tq == 0) {
                        float* o0 = out + ((size_t)(row0 + mt * 16 + g)) * (TSTEPS * 2)
                                        + (step - 1) * 2;
                        *(float2*)o0 = make_float2(co[0], co[1]);
                        *(float2*)(o0 + 8 * (TSTEPS * 2)) = make_float2(co[2], co[3]);
                    }
                } else {
#pragma unroll
                    for (int kt = 0; kt < 4; kt++) {
                        uint32_t ah[4];
                        ldmA(ah, abase + (((((uint32_t)kt << 1) | ub)) ^ xr) * 16u);
                        mma16816(ce, ah, EMBF[kt]);
                    }
                }
                uint32_t a = OFF_X + (uint32_t)mt * 2048u + stAddr0;
                *(uint32_t*)(smem + a)         = packh2(ce[0], ce[1]);
                *(uint32_t*)(smem + a + 1024u) = packh2(ce[2], ce[3]);
            }
        }
        barG(bid);

        // ===== GRU layers =====
#pragma unroll 1
        for (int lay = 0; lay < 3; lay++) {
            const uint32_t wb = fb + (uint32_t)(32 + lay * 192) * 256u + l8;
            uint2 WIR[4], WIZ[4], WIN[4], WHR[4], WHZ[4], WHN[4];
#pragma unroll
            for (int kt = 0; kt < 4; kt++) {
                WIR[kt] = ldB(wb + (uint32_t)(nj * 4 + kt) * 256u);
                WIZ[kt] = ldB(wb + (uint32_t)((nj + 8) * 4 + kt) * 256u);
                WIN[kt] = ldB(wb + (uint32_t)((nj + 16) * 4 + kt) * 256u);
                WHR[kt] = ldB(wb + (uint32_t)(96 + nj * 4 + kt) * 256u);
                WHZ[kt] = ldB(wb + (uint32_t)(96 + (nj + 8) * 4 + kt) * 256u);
                WHN[kt] = ldB(wb + (uint32_t)(96 + (nj + 16) * 4 + kt) * 256u);
            }
            const float br0 = ((const float*)(smem + OFF_BR))[lay * 64 + 8 * nj + 2 * tq];
            const float br1 = ((const float*)(smem + OFF_BR))[lay * 64 + 8 * nj + 2 * tq + 1];
            const float bz0 = ((const float*)(smem + OFF_BZ))[lay * 64 + 8 * nj + 2 * tq];
            const float bz1 = ((const float*)(smem + OFF_BZ))[lay * 64 + 8 * nj + 2 * tq + 1];
            const float bi0 = ((const float*)(smem + OFF_BIN))[lay * 64 + 8 * nj + 2 * tq];
            const float bi1 = ((const float*)(smem + OFF_BIN))[lay * 64 + 8 * nj + 2 * tq + 1];
            const float bh0 = ((const float*)(smem + OFF_BHN))[lay * 64 + 8 * nj + 2 * tq];
            const float bh1 = ((const float*)(smem + OFF_BHN))[lay * 64 + 8 * nj + 2 * tq + 1];
            const uint32_t xsrc = sb + ((lay == 0) ? OFF_X : hOffs[lay - 1]);
            const uint32_t hsrc = sb + hOffs[lay];
            const int ktho = nj >> 1;
            const int qho  = (nj & 1) << 1;

            uint32_t stash[8];
#pragma unroll 1
            for (int m = 0; m < 4; m++) {
                const int mt = mt0 + m;
                const uint32_t xb = xsrc + (uint32_t)mt * 2048u + lanerow;
                const uint32_t hb = hsrc + (uint32_t)mt * 2048u + lanerow;
                float cr[4] = {br0, br1, br0, br1};
                float cz[4] = {bz0, bz1, bz0, bz1};
                float ci[4] = {bi0, bi1, bi0, bi1};
                float ch[4] = {bh0, bh1, bh0, bh1};
                uint32_t ho0 = 0, ho1 = 0;
#pragma unroll
                for (int kt = 0; kt < 4; kt++) {
                    const uint32_t koff = (((((uint32_t)kt << 1) | ub)) ^ xr) * 16u;
                    uint32_t ax[4], ah[4];
                    ldmA(ax, xb + koff);
                    ldmA(ah, hb + koff);
                    mma16816(cr, ax, WIR[kt]);
                    mma16816(cr, ah, WHR[kt]);
                    mma16816(cz, ax, WIZ[kt]);
                    mma16816(cz, ah, WHZ[kt]);
                    mma16816(ci, ax, WIN[kt]);
                    mma16816(ch, ah, WHN[kt]);
                    if (kt == ktho) { ho0 = ah[qho]; ho1 = ah[qho + 1]; }
                }
                float2 f0 = __half22float2(*(__half2*)&ho0);
                float2 f1 = __half22float2(*(__half2*)&ho1);
                float h0 = gru1(cr[0], cz[0], ci[0], ch[0], f0.x);
                float h1 = gru1(cr[1], cz[1], ci[1], ch[1], f0.y);
                float h2 = gru1(cr[2], cz[2], ci[2], ch[2], f1.x);
                float h3 = gru1(cr[3], cz[3], ci[3], ch[3], f1.y);
                stash[2 * m]     = packh2(h0, h1);
                stash[2 * m + 1] = packh2(h2, h3);
            }
            barG(bid);   // all reads of h_l (this group) done
#pragma unroll
            for (int m = 0; m < 4; m++) {
                uint32_t a = hOffs[lay] + (uint32_t)(mt0 + m) * 2048u + stAddr0;
                *(uint32_t*)(smem + a)         = stash[2 * m];
                *(uint32_t*)(smem + a + 1024u) = stash[2 * m + 1];
            }
            barG(bid);   // h_l updated, visible to group
        }
    }

    // ===== final out (t = 127) from H2 =====
    if (outMt >= 0) {
        uint2 OUTF[4];
#pragma unroll
        for (int kt = 0; kt < 4; kt++)
            OUTF[kt] = ldB(fb + (uint32_t)(608 + kt) * 256u + l8);
        const uint32_t abase = sb + OFF_H2 + (uint32_t)outMt * 2048u + lanerow;
        float co[4] = {bo0, bo1, bo0, bo1};
#pragma unroll
        for (int kt = 0; kt < 4; kt++) {
            uint32_t ah[4];
            ldmA(ah, abase + (((((uint32_t)kt << 1) | ub)) ^ xr) * 16u);
            mma16816(co, ah, OUTF[kt]);
        }
        if (tq == 0) {
            float* o0 = out + ((size_t)(row0 + outMt * 16 + g)) * (TSTEPS * 2) + 127 * 2;
            *(float2*)o0 = make_float2(co[0], co[1]);
            *(float2*)(o0 + 8 * (TSTEPS * 2)) = make_float2(co[2], co[3]);
        }
    }
}

extern "C" void kernel_launch(void* const* d_in, const int* in_sizes, int n_in,
                              void* d_out, int out_size) {
    (void)in_sizes; (void)n_in; (void)out_size;
    const float* enc   = (const float*)d_in[0];
    const float* emb_w = (const float*)d_in[1];
    const float* emb_b = (const float*)d_in[2];
    const float* w_ih  = (const float*)d_in[3];
    const float* w_hh  = (const float*)d_in[4];
    const float* b_ih  = (const float*)d_in[5];
    const float* b_hh  = (const float*)d_in[6];
    const float* out_w = (const float*)d_in[7];
    const float* out_b = (const float*)d_in[8];
    float* out = (float*)d_out;

    cudaFuncSetAttribute(futuretraj_kernel,
                         cudaFuncAttributeMaxDynamicSharedMemorySize, SMEM_SZ);
    futuretraj_kernel<<<NCTA, NTH, SMEM_SZ>>>(
        enc, emb_w, emb_b, w_ih, w_hh, b_ih, b_hh, out_w, out_b, out);
}